// round 15
// baseline (speedup 1.0000x reference)
#include <cuda_runtime.h>
#include <cuda_fp16.h>
#include <cstdint>
#include <math.h>

#define BATCH 256
#define NCHK  512
#define NVAR  1024
#define DVd   3
#define DD    16
#define EE    3072

#define C_HID  388
#define V_HID  196
#define V_OUT  49

// Persistent message buffers
__device__ float g_Mc[(size_t)BATCH*EE*DD];   // 50.3 MB
__device__ float g_Mv[(size_t)BATCH*EE*DD];   // 50.3 MB

// var-of-edge table: voe[perm[p]] = p/3  (built once per launch)
__device__ int g_voe[EE];

// Fragment-ordered fp16x2 weight buffers (filled once per launch)
__device__ unsigned g_cW1f[7*7*6*64];         // [cc][nt7][kt6][lane][s2]
__device__ unsigned g_cW2f[7*12*4*64];        // [cc][nt12][ktl4][lane][s2]
__device__ unsigned g_vW1f[4*7*3*64];         // [cc][nt7][kt3][lane][s2]
__device__ unsigned g_vW2f[4*7*4*64];         // [cc][nt7][ktl4][lane][s2]

__device__ __forceinline__ unsigned packh2(float lo, float hi){
    __half2 h = __floats2half2_rn(lo, hi);
    return *reinterpret_cast<unsigned*>(&h);
}
__device__ __forceinline__ unsigned hadd2u(unsigned x, unsigned y){
    __half2 a = *reinterpret_cast<__half2*>(&x);
    __half2 b = *reinterpret_cast<__half2*>(&y);
    __half2 r = __hadd2(a, b);
    return *reinterpret_cast<unsigned*>(&r);
}
__device__ __forceinline__ unsigned hmul2u(unsigned x, unsigned y){
    __half2 a = *reinterpret_cast<__half2*>(&x);
    __half2 b = *reinterpret_cast<__half2*>(&y);
    __half2 r = __hmul2(a, b);
    return *reinterpret_cast<unsigned*>(&r);
}

// Packed tanh-gelu on packed f16x2 input
__device__ __forceinline__ unsigned gelu_h2p(unsigned xi){
    __half2 x = *reinterpret_cast<__half2*>(&xi);
    const __half2 A  = __floats2half2_rn(0.035677408f, 0.035677408f);
    const __half2 Bc = __floats2half2_rn(0.79788456f, 0.79788456f);
    const __half2 Hc = __floats2half2_rn(0.5f, 0.5f);
    __half2 u = __hmul2(x, x);
    __half2 v = __hmul2(u, x);
    __half2 tin = __hfma2(v, A, __hmul2(x, Bc));
    unsigned ti = *reinterpret_cast<unsigned*>(&tin);
    unsigned tu;
    asm("tanh.approx.f16x2 %0, %1;" : "=r"(tu) : "r"(ti));
    __half2 t = *reinterpret_cast<__half2*>(&tu);
    __half2 hx = __hmul2(x, Hc);
    __half2 r = __hfma2(hx, t, hx);
    return *reinterpret_cast<unsigned*>(&r);
}

// fp32-accumulator MMA (layer 2)
__device__ __forceinline__ void mma_f16(float* d, const unsigned* a, unsigned b0, unsigned b1){
    asm volatile("mma.sync.aligned.m16n8k16.row.col.f32.f16.f16.f32 "
        "{%0,%1,%2,%3},{%4,%5,%6,%7},{%8,%9},{%0,%1,%2,%3};"
        : "+f"(d[0]),"+f"(d[1]),"+f"(d[2]),"+f"(d[3])
        : "r"(a[0]),"r"(a[1]),"r"(a[2]),"r"(a[3]), "r"(b0),"r"(b1));
}
// fp16-accumulator MMA (layer 1): D regs are packed f16x2 {row gid, row gid+8}
__device__ __forceinline__ void mma_f16h(unsigned* d, const unsigned* a, unsigned b0, unsigned b1){
    asm volatile("mma.sync.aligned.m16n8k16.row.col.f16.f16.f16.f16 "
        "{%0,%1},{%2,%3,%4,%5},{%6,%7},{%0,%1};"
        : "+r"(d[0]),"+r"(d[1])
        : "r"(a[0]),"r"(a[1]),"r"(a[2]),"r"(a[3]), "r"(b0),"r"(b1));
}

// ---------------------------------------------------------------------------
__global__ void prep_voe(const int* __restrict__ perm)
{
    int p = blockIdx.x * blockDim.x + threadIdx.x;
    if (p < EE) g_voe[perm[p]] = p / DVd;
}

__global__ void prep_check(const float* __restrict__ W1, const float* __restrict__ W2)
{
    int idx = blockIdx.x*blockDim.x + threadIdx.x;
    if (idx < 18816) {
        int l = (idx >> 1) & 31;
        int s = idx & 1;
        int r = idx >> 6;
        int kt = r % 6; r /= 6;
        int nt = r % 7; int cc = r / 7;
        int gid = l >> 2, tig = l & 3;
        int k0 = kt*16 + 2*tig + 8*s;
        int n  = cc*56 + nt*8 + gid;
        float f0 = (n < C_HID) ? W1[k0*C_HID + n] : 0.0f;
        float f1 = (n < C_HID) ? W1[(k0+1)*C_HID + n] : 0.0f;
        g_cW1f[idx] = packh2(f0, f1);
    } else if (idx < 40320) {
        int j = idx - 18816;
        int l = (j >> 1) & 31;
        int s = j & 1;
        int r = j >> 6;
        int ktl = r % 4; r /= 4;
        int nt = r % 12; int cc = r / 12;
        int gid = l >> 2, tig = l & 3;
        int kl   = ktl*16 + 2*tig + 8*s;
        int khid = cc*56 + kl;
        int n    = nt*8 + gid;
        bool ok = (kl < 56) && (khid < C_HID);
        float f0 = ok ? W2[khid*96 + n] : 0.0f;
        float f1 = ok ? W2[(khid+1)*96 + n] : 0.0f;
        g_cW2f[j] = packh2(f0, f1);
    }
}

__global__ void prep_var(const float* __restrict__ W1, const float* __restrict__ W2)
{
    int idx = blockIdx.x*blockDim.x + threadIdx.x;
    if (idx < 5376) {
        int l = (idx >> 1) & 31;
        int s = idx & 1;
        int r = idx >> 6;
        int kt = r % 3; r /= 3;
        int nt = r % 7; int cc = r / 7;
        int gid = l >> 2, tig = l & 3;
        int k0 = kt*16 + 2*tig + 8*s;
        int n  = cc*56 + nt*8 + gid;
        float f0 = (n < V_HID) ? W1[k0*V_HID + n] : 0.0f;
        float f1 = (n < V_HID) ? W1[(k0+1)*V_HID + n] : 0.0f;
        g_vW1f[idx] = packh2(f0, f1);
    } else if (idx < 12544) {
        int j = idx - 5376;
        int l = (j >> 1) & 31;
        int s = j & 1;
        int r = j >> 6;
        int ktl = r % 4; r /= 4;
        int nt = r % 7; int cc = r / 7;
        int gid = l >> 2, tig = l & 3;
        int kl   = ktl*16 + 2*tig + 8*s;
        int khid = cc*56 + kl;
        int n    = nt*8 + gid;
        bool ok = (kl < 56) && (khid < V_HID) && (n < V_OUT);
        float f0 = ok ? W2[khid*V_OUT + n] : 0.0f;
        float f1 = ok ? W2[(khid+1)*V_OUT + n] : 0.0f;
        g_vW2f[j] = packh2(f0, f1);
    }
}

// ---------------------------------------------------------------------------
// CHECK: 131072 rows. 256 thr, 8 warps x m16, 128 rows/CTA, 3 CTAs/SM.
// Layer-1 accumulator in packed fp16 (acc1 = 14 regs); layer-2 in fp32.
// ---------------------------------------------------------------------------
#define SHS 36

__global__ __launch_bounds__(256, 3)
void check_kernel(const int* __restrict__ synd,
                  const float* __restrict__ W1raw, const float* __restrict__ B1,
                  const float* __restrict__ B2,
                  const float* __restrict__ prior, int t0)
{
    extern __shared__ unsigned smem[];
    uint4*    sX   = (uint4*)smem;                 // 8w*6kt*32 = 1536 uint4
    unsigned* sH   = smem + 6144;                  // 8*16*36 = 4608 words
    unsigned* sb1h = sH + 8*16*SHS;                // 196 packed h2
    unsigned* sw1h = sb1h + 196;                   // 196 packed h2
    float*    sb2  = (float*)(sw1h + 196);         // 96

    const int tid  = threadIdx.x;
    const int warp = tid >> 5, lane = tid & 31;
    const int gid  = lane >> 2, tig = lane & 3;
    const int base_row = blockIdx.x * 128;
    const int r0 = base_row + warp*16 + gid, r1 = r0 + 8;

    // ---- prologue: packed bias / w1row (column pairs) ----
    for (int i = tid; i < 196; i += 256) {
        int cc = i / 28, r = i % 28;
        int nt = r >> 2, tg = r & 3;
        int c0 = cc*56 + nt*8 + 2*tg;
        float b0v = (c0     < C_HID) ? B1[c0]     : 0.0f;
        float b1v = (c0 + 1 < C_HID) ? B1[c0 + 1] : 0.0f;
        sb1h[i] = packh2(b0v, b1v);
        float w0v = (c0     < C_HID) ? W1raw[96*C_HID + c0]     : 0.0f;
        float w1v = (c0 + 1 < C_HID) ? W1raw[96*C_HID + c0 + 1] : 0.0f;
        sw1h[i] = packh2(w0v, w1v);
    }
    if (tid < 96) sb2[tid] = B2[tid];

    // stage A fragments (fp16x2)
    {
        uint4* dst = sX + warp*6*32 + lane;
        if (t0) {
            int e0 = (r0 & (NCHK-1)) * 6;
            int e1 = (r1 & (NCHK-1)) * 6;
            #pragma unroll
            for (int kt = 0; kt < 6; kt++) {
                float v0 = 0.0f, v1 = 0.0f;
                if (tig == 0) {
                    v0 = prior[g_voe[e0 + kt]];
                    v1 = prior[g_voe[e1 + kt]];
                }
                uint4 v;
                v.x = packh2(v0, 0.0f);
                v.y = packh2(v1, 0.0f);
                v.z = 0u; v.w = 0u;
                dst[kt*32] = v;
            }
        } else {
            const float* x0 = g_Mc + (size_t)r0 * 96;
            const float* x1 = g_Mc + (size_t)r1 * 96;
            #pragma unroll
            for (int kt = 0; kt < 6; kt++) {
                int c = kt*16 + 2*tig;
                float2 p00 = *(const float2*)(x0 + c);
                float2 p01 = *(const float2*)(x0 + c + 8);
                float2 p10 = *(const float2*)(x1 + c);
                float2 p11 = *(const float2*)(x1 + c + 8);
                uint4 v;
                v.x = packh2(p00.x, p00.y);
                v.y = packh2(p10.x, p10.y);
                v.z = packh2(p01.x, p01.y);
                v.w = packh2(p11.x, p11.y);
                dst[kt*32] = v;
            }
        }
    }
    const float sg0 = 1.0f - 2.0f * (float)synd[r0];
    const float sg1 = 1.0f - 2.0f * (float)synd[r1];
    const unsigned sg0h = packh2(sg0, sg0);
    const unsigned sg1h = packh2(sg1, sg1);

    // zero pad words (k_local 56..63) in this warp's H region
    unsigned* sHw = sH + warp*16*SHS;
    for (int i = lane; i < 64; i += 32) {
        int rr = i >> 2, w = 28 + (i & 3);
        sHw[rr*SHS + w] = 0;
    }
    __syncthreads();

    float acc2[12][4];
    #pragma unroll
    for (int n = 0; n < 12; n++)
        #pragma unroll
        for (int i = 0; i < 4; i++) acc2[n][i] = 0.0f;

    const uint4* myX = sX + warp*6*32 + lane;

    for (int cc = 0; cc < 7; cc++) {
        // ---- layer 1 (fp16 acc): m16 x n56, K=96, rank-1 sgn init ----
        unsigned acc1[7][2];
        #pragma unroll
        for (int nt = 0; nt < 7; nt++) {
            unsigned w = sw1h[cc*28 + nt*4 + tig];
            acc1[nt][0] = hmul2u(sg0h, w);
            acc1[nt][1] = hmul2u(sg1h, w);
        }
        const uint2* wp1 = (const uint2*)g_cW1f + (size_t)cc*1344 + lane;
        #pragma unroll
        for (int kt = 0; kt < 6; kt++) {
            uint4 a4 = myX[kt*32];
            unsigned a[4] = {a4.x, a4.y, a4.z, a4.w};
            #pragma unroll
            for (int nt = 0; nt < 7; nt++) {
                uint2 b = __ldg(wp1 + (size_t)(nt*6 + kt)*32);
                mma_f16h(acc1[nt], a, b.x, b.y);
            }
        }

        // ---- packed bias + gelu -> warp-private H (f16x2 words) ----
        #pragma unroll
        for (int nt = 0; nt < 7; nt++) {
            unsigned bb = sb1h[cc*28 + nt*4 + tig];
            sHw[gid*SHS      + nt*4 + tig] = gelu_h2p(hadd2u(acc1[nt][0], bb));
            sHw[(gid+8)*SHS  + nt*4 + tig] = gelu_h2p(hadd2u(acc1[nt][1], bb));
        }
        __syncwarp();

        // ---- layer 2 partial (fp32 acc): m16 x n96, K=64 ----
        const uint2* wp2 = (const uint2*)g_cW2f + (size_t)cc*1536 + lane;
        #pragma unroll
        for (int ktl = 0; ktl < 4; ktl++) {
            unsigned a[4];
            a[0] = sHw[gid*SHS     + ktl*8 + tig];
            a[1] = sHw[(gid+8)*SHS + ktl*8 + tig];
            a[2] = sHw[gid*SHS     + ktl*8 + tig + 4];
            a[3] = sHw[(gid+8)*SHS + ktl*8 + tig + 4];
            #pragma unroll
            for (int nt = 0; nt < 12; nt++) {
                uint2 b = __ldg(wp2 + (size_t)(nt*4 + ktl)*32);
                mma_f16(acc2[nt], a, b.x, b.y);
            }
        }
        __syncwarp();
    }

    // ---- epilogue: Mv = (D + b2) * sgn ----
    #pragma unroll
    for (int nt = 0; nt < 12; nt++) {
        int col = nt*8 + 2*tig;
        float bb0 = sb2[col], bb1 = sb2[col+1];
        float2 y0, y1;
        y0.x = (acc2[nt][0] + bb0) * sg0;
        y0.y = (acc2[nt][1] + bb1) * sg0;
        y1.x = (acc2[nt][2] + bb0) * sg1;
        y1.y = (acc2[nt][3] + bb1) * sg1;
        *(float2*)(g_Mv + (size_t)r0*96 + col) = y0;
        *(float2*)(g_Mv + (size_t)r1*96 + col) = y1;
    }
}

// ---------------------------------------------------------------------------
// VAR: 262144 rows. Same structure; gather/scatter via perm. 3 CTAs/SM.
// ---------------------------------------------------------------------------
__global__ __launch_bounds__(256, 3)
void var_kernel(const int* __restrict__ perm,
                const float* __restrict__ prior,
                const float* __restrict__ W1raw, const float* __restrict__ B1,
                const float* __restrict__ B2,
                float* __restrict__ out_llr)
{
    extern __shared__ unsigned smemv[];
    uint4*    sX   = (uint4*)smemv;                // 768 uint4
    unsigned* sH   = smemv + 3072;                 // 4608 words
    unsigned* sb1h = sH + 8*16*SHS;                // 112 packed h2
    unsigned* sw1h = sb1h + 112;                   // 112 packed h2
    float*    sb2  = (float*)(sw1h + 112);         // 49

    const int tid  = threadIdx.x;
    const int warp = tid >> 5, lane = tid & 31;
    const int gid  = lane >> 2, tig = lane & 3;
    const int base_row = blockIdx.x * 128;
    const int r0 = base_row + warp*16 + gid, r1 = r0 + 8;
    const int b0i = r0 >> 10, v0 = r0 & 1023;
    const int b1i = r1 >> 10, v1 = r1 & 1023;

    for (int i = tid; i < 112; i += 256) {
        int cc = i / 28, r = i % 28;
        int nt = r >> 2, tg = r & 3;
        int c0 = cc*56 + nt*8 + 2*tg;
        float b0v = (c0     < V_HID) ? B1[c0]     : 0.0f;
        float b1v = (c0 + 1 < V_HID) ? B1[c0 + 1] : 0.0f;
        sb1h[i] = packh2(b0v, b1v);
        float w0v = (c0     < V_HID) ? W1raw[48*V_HID + c0]     : 0.0f;
        float w1v = (c0 + 1 < V_HID) ? W1raw[48*V_HID + c0 + 1] : 0.0f;
        sw1h[i] = packh2(w0v, w1v);
    }
    if (tid < 49) sb2[tid] = B2[tid];

    int p0[3], p1[3];
    #pragma unroll
    for (int e = 0; e < 3; e++) {
        p0[e] = perm[v0*DVd + e];
        p1[e] = perm[v1*DVd + e];
    }
    const float pr0 = prior[v0], pr1 = prior[v1];
    const unsigned pr0h = packh2(pr0, pr0);
    const unsigned pr1h = packh2(pr1, pr1);

    // stage A fragments: kt = e (16 cols per edge)
    {
        const float* base0 = g_Mv + (size_t)b0i*EE*DD;
        const float* base1 = g_Mv + (size_t)b1i*EE*DD;
        uint4* dst = sX + warp*3*32 + lane;
        #pragma unroll
        for (int kt = 0; kt < 3; kt++) {
            const float* q0 = base0 + p0[kt]*DD;
            const float* q1 = base1 + p1[kt]*DD;
            int c = 2*tig;
            float2 p00 = *(const float2*)(q0 + c);
            float2 p01 = *(const float2*)(q0 + c + 8);
            float2 p10 = *(const float2*)(q1 + c);
            float2 p11 = *(const float2*)(q1 + c + 8);
            uint4 v;
            v.x = packh2(p00.x, p00.y);
            v.y = packh2(p10.x, p10.y);
            v.z = packh2(p01.x, p01.y);
            v.w = packh2(p11.x, p11.y);
            dst[kt*32] = v;
        }
    }

    unsigned* sHw = sH + warp*16*SHS;
    for (int i = lane; i < 64; i += 32) {
        int rr = i >> 2, w = 28 + (i & 3);
        sHw[rr*SHS + w] = 0;
    }
    __syncthreads();

    float acc2[7][4];
    #pragma unroll
    for (int n = 0; n < 7; n++)
        #pragma unroll
        for (int i = 0; i < 4; i++) acc2[n][i] = 0.0f;

    const uint4* myX = sX + warp*3*32 + lane;

    for (int cc = 0; cc < 4; cc++) {
        // ---- layer 1 (fp16 acc): K=48, rank-1 prior init ----
        unsigned acc1[7][2];
        #pragma unroll
        for (int nt = 0; nt < 7; nt++) {
            unsigned w = sw1h[cc*28 + nt*4 + tig];
            acc1[nt][0] = hmul2u(pr0h, w);
            acc1[nt][1] = hmul2u(pr1h, w);
        }
        const uint2* wp1 = (const uint2*)g_vW1f + (size_t)cc*672 + lane;
        #pragma unroll
        for (int kt = 0; kt < 3; kt++) {
            uint4 a4 = myX[kt*32];
            unsigned a[4] = {a4.x, a4.y, a4.z, a4.w};
            #pragma unroll
            for (int nt = 0; nt < 7; nt++) {
                uint2 b = __ldg(wp1 + (size_t)(nt*3 + kt)*32);
                mma_f16h(acc1[nt], a, b.x, b.y);
            }
        }

        #pragma unroll
        for (int nt = 0; nt < 7; nt++) {
            unsigned bb = sb1h[cc*28 + nt*4 + tig];
            sHw[gid*SHS      + nt*4 + tig] = gelu_h2p(hadd2u(acc1[nt][0], bb));
            sHw[(gid+8)*SHS  + nt*4 + tig] = gelu_h2p(hadd2u(acc1[nt][1], bb));
        }
        __syncwarp();

        const uint2* wp2 = (const uint2*)g_vW2f + (size_t)cc*896 + lane;
        #pragma unroll
        for (int ktl = 0; ktl < 4; ktl++) {
            unsigned a[4];
            a[0] = sHw[gid*SHS     + ktl*8 + tig];
            a[1] = sHw[(gid+8)*SHS + ktl*8 + tig];
            a[2] = sHw[gid*SHS     + ktl*8 + tig + 4];
            a[3] = sHw[(gid+8)*SHS + ktl*8 + tig + 4];
            #pragma unroll
            for (int nt = 0; nt < 7; nt++) {
                uint2 b = __ldg(wp2 + (size_t)(nt*4 + ktl)*32);
                mma_f16(acc2[nt], a, b.x, b.y);
            }
        }
        __syncwarp();
    }

    // ---- epilogue: float2 scatter via perm regs; col 48 -> llr ----
    #pragma unroll
    for (int nt = 0; nt < 6; nt++) {
        int col = nt*8 + 2*tig;              // even, < 48
        int e = col >> 4, d = col & 15;
        float bb0 = sb2[col], bb1 = sb2[col+1];
        {
            float2 y;
            y.x = acc2[nt][0] + bb0;
            y.y = acc2[nt][1] + bb1;
            *(float2*)(g_Mc + ((size_t)b0i*EE + p0[e])*DD + d) = y;
        }
        {
            float2 y;
            y.x = acc2[nt][2] + bb0;
            y.y = acc2[nt][3] + bb1;
            *(float2*)(g_Mc + ((size_t)b1i*EE + p1[e])*DD + d) = y;
        }
    }
    if (tig == 0) {
        float bb = sb2[48];
        out_llr[r0] = acc2[6][0] + bb;
        out_llr[r1] = acc2[6][2] + bb;
    }
}

// ---------------------------------------------------------------------------
extern "C" void kernel_launch(void* const* d_in, const int* in_sizes, int n_in,
                              void* d_out, int out_size)
{
    const int*   synd  = (const int*)  d_in[0];
    const float* prior = (const float*)d_in[2];
    const int*   perm  = (const int*)  d_in[3];
    const float* cW1   = (const float*)d_in[4];
    const float* cb1   = (const float*)d_in[5];
    const float* cW2   = (const float*)d_in[6];
    const float* cb2   = (const float*)d_in[7];
    const float* vW1   = (const float*)d_in[8];
    const float* vb1   = (const float*)d_in[9];
    const float* vW2   = (const float*)d_in[10];
    const float* vb2   = (const float*)d_in[11];
    float* out = (float*)d_out;

    const int T = out_size / (BATCH * NVAR);

    const int check_smem = (6144 + 4608 + 196 + 196)*4 + 96*4 + 64;   // ~44.8 KB
    const int var_smem   = (3072 + 4608 + 112 + 112)*4 + 49*4 + 64;   // ~31.8 KB

    cudaFuncSetAttribute(check_kernel, cudaFuncAttributeMaxDynamicSharedMemorySize, check_smem);
    cudaFuncSetAttribute(var_kernel,   cudaFuncAttributeMaxDynamicSharedMemorySize, var_smem);

    prep_voe<<<(EE + 255)/256, 256>>>(perm);
    prep_check<<<(40320 + 255)/256, 256>>>(cW1, cW2);
    prep_var<<<(12544 + 255)/256, 256>>>(vW1, vW2);

    const int check_blocks = (BATCH*NCHK) / 128;   // 1024
    const int var_blocks   = (BATCH*NVAR) / 128;   // 2048

    for (int t = 0; t < T; t++) {
        check_kernel<<<check_blocks, 256, check_smem>>>(synd, cW1, cb1, cb2,
                                                        prior, t == 0 ? 1 : 0);
        var_kernel<<<var_blocks, 256, var_smem>>>(perm, prior, vW1, vb1, vb2,
                                                  out + (size_t)t * BATCH * NVAR);
    }
}

// round 16
// speedup vs baseline: 1.2860x; 1.2860x over previous
#include <cuda_runtime.h>
#include <cuda_fp16.h>
#include <cstdint>
#include <math.h>

#define BATCH 256
#define NCHK  512
#define NVAR  1024
#define DVd   3
#define DD    16
#define EE    3072

#define C_HID  388
#define V_HID  196
#define V_OUT  49

// Persistent message buffers
__device__ float g_Mc[(size_t)BATCH*EE*DD];   // 50.3 MB
__device__ float g_Mv[(size_t)BATCH*EE*DD];   // 50.3 MB

// var-of-edge table: voe[perm[p]] = p/3  (built once per launch)
__device__ int g_voe[EE];

// Fragment-ordered fp16x2 weight buffers (filled once per launch)
__device__ unsigned g_cW1f[7*7*3*128];        // [cc][nt7][ktp3][lane][4w]
__device__ unsigned g_cW2f[7*12*2*128];       // [cc][nt12][ktlp2][lane][4w]
__device__ unsigned g_vW1f[4*7*3*64];         // [cc][nt7][kt3][lane][2w]
__device__ unsigned g_vW2f[4*7*2*128];        // [cc][nt7][ktlp2][lane][4w]

__device__ __forceinline__ unsigned packh2(float lo, float hi){
    __half2 h = __floats2half2_rn(lo, hi);
    return *reinterpret_cast<unsigned*>(&h);
}
__device__ __forceinline__ unsigned hadd2u(unsigned x, unsigned y){
    __half2 a = *reinterpret_cast<__half2*>(&x);
    __half2 b = *reinterpret_cast<__half2*>(&y);
    __half2 r = __hadd2(a, b);
    return *reinterpret_cast<unsigned*>(&r);
}
__device__ __forceinline__ unsigned hmul2u(unsigned x, unsigned y){
    __half2 a = *reinterpret_cast<__half2*>(&x);
    __half2 b = *reinterpret_cast<__half2*>(&y);
    __half2 r = __hmul2(a, b);
    return *reinterpret_cast<unsigned*>(&r);
}

// Packed tanh-gelu on packed f16x2 input
__device__ __forceinline__ unsigned gelu_h2p(unsigned xi){
    __half2 x = *reinterpret_cast<__half2*>(&xi);
    const __half2 A  = __floats2half2_rn(0.035677408f, 0.035677408f);
    const __half2 Bc = __floats2half2_rn(0.79788456f, 0.79788456f);
    const __half2 Hc = __floats2half2_rn(0.5f, 0.5f);
    __half2 u = __hmul2(x, x);
    __half2 v = __hmul2(u, x);
    __half2 tin = __hfma2(v, A, __hmul2(x, Bc));
    unsigned ti = *reinterpret_cast<unsigned*>(&tin);
    unsigned tu;
    asm("tanh.approx.f16x2 %0, %1;" : "=r"(tu) : "r"(ti));
    __half2 t = *reinterpret_cast<__half2*>(&tu);
    __half2 hx = __hmul2(x, Hc);
    __half2 r = __hfma2(hx, t, hx);
    return *reinterpret_cast<unsigned*>(&r);
}

// fp32-accumulator MMA (layer 2)
__device__ __forceinline__ void mma_f16(float* d, const unsigned* a, unsigned b0, unsigned b1){
    asm volatile("mma.sync.aligned.m16n8k16.row.col.f32.f16.f16.f32 "
        "{%0,%1,%2,%3},{%4,%5,%6,%7},{%8,%9},{%0,%1,%2,%3};"
        : "+f"(d[0]),"+f"(d[1]),"+f"(d[2]),"+f"(d[3])
        : "r"(a[0]),"r"(a[1]),"r"(a[2]),"r"(a[3]), "r"(b0),"r"(b1));
}
// fp16-accumulator MMA (layer 1)
__device__ __forceinline__ void mma_f16h(unsigned* d, const unsigned* a, unsigned b0, unsigned b1){
    asm volatile("mma.sync.aligned.m16n8k16.row.col.f16.f16.f16.f16 "
        "{%0,%1},{%2,%3,%4,%5},{%6,%7},{%0,%1};"
        : "+r"(d[0]),"+r"(d[1])
        : "r"(a[0]),"r"(a[1]),"r"(a[2]),"r"(a[3]), "r"(b0),"r"(b1));
}

// ---------------------------------------------------------------------------
__global__ void prep_voe(const int* __restrict__ perm)
{
    int p = blockIdx.x * blockDim.x + threadIdx.x;
    if (p < EE) g_voe[perm[p]] = p / DVd;
}

__global__ void prep_check(const float* __restrict__ W1, const float* __restrict__ W2)
{
    int idx = blockIdx.x*blockDim.x + threadIdx.x;
    if (idx < 18816) {
        int w = idx & 3, lane = (idx >> 2) & 31;
        int r = idx >> 7;
        int ktp = r % 3; r /= 3;
        int nt = r % 7;  int cc = r / 7;
        int gid = lane >> 2, tig = lane & 3;
        int kt = ktp*2 + (w >> 1), s = w & 1;
        int k0 = kt*16 + 2*tig + 8*s;
        int n  = cc*56 + nt*8 + gid;
        float f0 = (n < C_HID) ? W1[k0*C_HID + n] : 0.0f;
        float f1 = (n < C_HID) ? W1[(k0+1)*C_HID + n] : 0.0f;
        g_cW1f[idx] = packh2(f0, f1);
    } else if (idx < 40320) {
        int j = idx - 18816;
        int w = j & 3, lane = (j >> 2) & 31;
        int r = j >> 7;
        int ktlp = r % 2; r /= 2;
        int nt = r % 12; int cc = r / 12;
        int gid = lane >> 2, tig = lane & 3;
        int ktl = ktlp*2 + (w >> 1), s = w & 1;
        int kl   = ktl*16 + 2*tig + 8*s;
        int khid = cc*56 + kl;
        int n    = nt*8 + gid;
        bool ok = (kl < 56) && (khid < C_HID);
        float f0 = ok ? W2[khid*96 + n] : 0.0f;
        float f1 = ok ? W2[(khid+1)*96 + n] : 0.0f;
        g_cW2f[j] = packh2(f0, f1);
    }
}

__global__ void prep_var(const float* __restrict__ W1, const float* __restrict__ W2)
{
    int idx = blockIdx.x*blockDim.x + threadIdx.x;
    if (idx < 5376) {
        int l = (idx >> 1) & 31;
        int s = idx & 1;
        int r = idx >> 6;
        int kt = r % 3; r /= 3;
        int nt = r % 7; int cc = r / 7;
        int gid = l >> 2, tig = l & 3;
        int k0 = kt*16 + 2*tig + 8*s;
        int n  = cc*56 + nt*8 + gid;
        float f0 = (n < V_HID) ? W1[k0*V_HID + n] : 0.0f;
        float f1 = (n < V_HID) ? W1[(k0+1)*V_HID + n] : 0.0f;
        g_vW1f[idx] = packh2(f0, f1);
    } else if (idx < 12544) {
        int j = idx - 5376;
        int w = j & 3, lane = (j >> 2) & 31;
        int r = j >> 7;
        int ktlp = r % 2; r /= 2;
        int nt = r % 7; int cc = r / 7;
        int gid = lane >> 2, tig = lane & 3;
        int ktl = ktlp*2 + (w >> 1), s = w & 1;
        int kl   = ktl*16 + 2*tig + 8*s;
        int khid = cc*56 + kl;
        int n    = nt*8 + gid;
        bool ok = (kl < 56) && (khid < V_HID) && (n < V_OUT);
        float f0 = ok ? W2[khid*V_OUT + n] : 0.0f;
        float f1 = ok ? W2[(khid+1)*V_OUT + n] : 0.0f;
        g_vW2f[j] = packh2(f0, f1);
    }
}

// ---------------------------------------------------------------------------
// CHECK: 131072 rows. 256 thr, 8 warps x m16, 128 rows/CTA, 2 CTAs/SM.
// fp16-acc layer 1 + packed gelu; uint4 B loads (k-tile pairs).
// ---------------------------------------------------------------------------
#define SHS 36

__global__ __launch_bounds__(256, 2)
void check_kernel(const int* __restrict__ synd,
                  const float* __restrict__ W1raw, const float* __restrict__ B1,
                  const float* __restrict__ B2,
                  const float* __restrict__ prior, int t0)
{
    extern __shared__ unsigned smem[];
    uint4*    sX   = (uint4*)smem;                 // 8w*6kt*32 = 1536 uint4
    unsigned* sH   = smem + 6144;                  // 8*16*36 = 4608 words
    unsigned* sb1h = sH + 8*16*SHS;                // 196 packed h2
    unsigned* sw1h = sb1h + 196;                   // 196 packed h2
    float*    sb2  = (float*)(sw1h + 196);         // 96

    const int tid  = threadIdx.x;
    const int warp = tid >> 5, lane = tid & 31;
    const int gid  = lane >> 2, tig = lane & 3;
    const int base_row = blockIdx.x * 128;
    const int r0 = base_row + warp*16 + gid, r1 = r0 + 8;

    // ---- prologue: packed bias / w1row (column pairs) ----
    for (int i = tid; i < 196; i += 256) {
        int cc = i / 28, r = i % 28;
        int nt = r >> 2, tg = r & 3;
        int c0 = cc*56 + nt*8 + 2*tg;
        float b0v = (c0     < C_HID) ? B1[c0]     : 0.0f;
        float b1v = (c0 + 1 < C_HID) ? B1[c0 + 1] : 0.0f;
        sb1h[i] = packh2(b0v, b1v);
        float w0v = (c0     < C_HID) ? W1raw[96*C_HID + c0]     : 0.0f;
        float w1v = (c0 + 1 < C_HID) ? W1raw[96*C_HID + c0 + 1] : 0.0f;
        sw1h[i] = packh2(w0v, w1v);
    }
    if (tid < 96) sb2[tid] = B2[tid];

    // stage A fragments (fp16x2)
    {
        uint4* dst = sX + warp*6*32 + lane;
        if (t0) {
            int e0 = (r0 & (NCHK-1)) * 6;
            int e1 = (r1 & (NCHK-1)) * 6;
            #pragma unroll
            for (int kt = 0; kt < 6; kt++) {
                float v0 = 0.0f, v1 = 0.0f;
                if (tig == 0) {
                    v0 = prior[g_voe[e0 + kt]];
                    v1 = prior[g_voe[e1 + kt]];
                }
                uint4 v;
                v.x = packh2(v0, 0.0f);
                v.y = packh2(v1, 0.0f);
                v.z = 0u; v.w = 0u;
                dst[kt*32] = v;
            }
        } else {
            const float* x0 = g_Mc + (size_t)r0 * 96;
            const float* x1 = g_Mc + (size_t)r1 * 96;
            #pragma unroll
            for (int kt = 0; kt < 6; kt++) {
                int c = kt*16 + 2*tig;
                float2 p00 = *(const float2*)(x0 + c);
                float2 p01 = *(const float2*)(x0 + c + 8);
                float2 p10 = *(const float2*)(x1 + c);
                float2 p11 = *(const float2*)(x1 + c + 8);
                uint4 v;
                v.x = packh2(p00.x, p00.y);
                v.y = packh2(p10.x, p10.y);
                v.z = packh2(p01.x, p01.y);
                v.w = packh2(p11.x, p11.y);
                dst[kt*32] = v;
            }
        }
    }
    const float sg0 = 1.0f - 2.0f * (float)synd[r0];
    const float sg1 = 1.0f - 2.0f * (float)synd[r1];
    const unsigned sg0h = packh2(sg0, sg0);
    const unsigned sg1h = packh2(sg1, sg1);

    // zero pad words (k_local 56..63) in this warp's H region
    unsigned* sHw = sH + warp*16*SHS;
    for (int i = lane; i < 64; i += 32) {
        int rr = i >> 2, w = 28 + (i & 3);
        sHw[rr*SHS + w] = 0;
    }
    __syncthreads();

    float acc2[12][4];
    #pragma unroll
    for (int n = 0; n < 12; n++)
        #pragma unroll
        for (int i = 0; i < 4; i++) acc2[n][i] = 0.0f;

    const uint4* myX = sX + warp*6*32 + lane;

    for (int cc = 0; cc < 7; cc++) {
        // ---- layer 1 (fp16 acc): m16 x n56, K=96, rank-1 sgn init ----
        unsigned acc1[7][2];
        #pragma unroll
        for (int nt = 0; nt < 7; nt++) {
            unsigned w = sw1h[cc*28 + nt*4 + tig];
            acc1[nt][0] = hmul2u(sg0h, w);
            acc1[nt][1] = hmul2u(sg1h, w);
        }
        const uint4* wp1 = (const uint4*)g_cW1f + (size_t)cc*672 + lane;
        #pragma unroll
        for (int ktp = 0; ktp < 3; ktp++) {
            uint4 a04 = myX[(2*ktp)*32];
            uint4 a14 = myX[(2*ktp+1)*32];
            unsigned a0[4] = {a04.x, a04.y, a04.z, a04.w};
            unsigned a1[4] = {a14.x, a14.y, a14.z, a14.w};
            #pragma unroll
            for (int nt = 0; nt < 7; nt++) {
                uint4 b = __ldg(wp1 + (size_t)(nt*3 + ktp)*32);
                mma_f16h(acc1[nt], a0, b.x, b.y);
                mma_f16h(acc1[nt], a1, b.z, b.w);
            }
        }

        // ---- packed bias + gelu -> warp-private H (f16x2 words) ----
        #pragma unroll
        for (int nt = 0; nt < 7; nt++) {
            unsigned bb = sb1h[cc*28 + nt*4 + tig];
            sHw[gid*SHS      + nt*4 + tig] = gelu_h2p(hadd2u(acc1[nt][0], bb));
            sHw[(gid+8)*SHS  + nt*4 + tig] = gelu_h2p(hadd2u(acc1[nt][1], bb));
        }
        __syncwarp();

        // ---- layer 2 partial (fp32 acc): m16 x n96, K=64 ----
        const uint4* wp2 = (const uint4*)g_cW2f + (size_t)cc*768 + lane;
        #pragma unroll
        for (int ktlp = 0; ktlp < 2; ktlp++) {
            int w0 = (2*ktlp)*8 + tig;
            int w1 = w0 + 8;
            unsigned a0[4] = { sHw[gid*SHS + w0],     sHw[(gid+8)*SHS + w0],
                               sHw[gid*SHS + w0 + 4], sHw[(gid+8)*SHS + w0 + 4] };
            unsigned a1[4] = { sHw[gid*SHS + w1],     sHw[(gid+8)*SHS + w1],
                               sHw[gid*SHS + w1 + 4], sHw[(gid+8)*SHS + w1 + 4] };
            #pragma unroll
            for (int nt = 0; nt < 12; nt++) {
                uint4 b = __ldg(wp2 + (size_t)(nt*2 + ktlp)*32);
                mma_f16(acc2[nt], a0, b.x, b.y);
                mma_f16(acc2[nt], a1, b.z, b.w);
            }
        }
        __syncwarp();
    }

    // ---- epilogue: Mv = (D + b2) * sgn ----
    #pragma unroll
    for (int nt = 0; nt < 12; nt++) {
        int col = nt*8 + 2*tig;
        float bb0 = sb2[col], bb1 = sb2[col+1];
        float2 y0, y1;
        y0.x = (acc2[nt][0] + bb0) * sg0;
        y0.y = (acc2[nt][1] + bb1) * sg0;
        y1.x = (acc2[nt][2] + bb0) * sg1;
        y1.y = (acc2[nt][3] + bb1) * sg1;
        *(float2*)(g_Mv + (size_t)r0*96 + col) = y0;
        *(float2*)(g_Mv + (size_t)r1*96 + col) = y1;
    }
}

// ---------------------------------------------------------------------------
// VAR: 262144 rows. Same structure; gather/scatter via perm. 2 CTAs/SM.
// ---------------------------------------------------------------------------
__global__ __launch_bounds__(256, 2)
void var_kernel(const int* __restrict__ perm,
                const float* __restrict__ prior,
                const float* __restrict__ W1raw, const float* __restrict__ B1,
                const float* __restrict__ B2,
                float* __restrict__ out_llr)
{
    extern __shared__ unsigned smemv[];
    uint4*    sX   = (uint4*)smemv;                // 768 uint4
    unsigned* sH   = smemv + 3072;                 // 4608 words
    unsigned* sb1h = sH + 8*16*SHS;                // 112 packed h2
    unsigned* sw1h = sb1h + 112;                   // 112 packed h2
    float*    sb2  = (float*)(sw1h + 112);         // 49

    const int tid  = threadIdx.x;
    const int warp = tid >> 5, lane = tid & 31;
    const int gid  = lane >> 2, tig = lane & 3;
    const int base_row = blockIdx.x * 128;
    const int r0 = base_row + warp*16 + gid, r1 = r0 + 8;
    const int b0i = r0 >> 10, v0 = r0 & 1023;
    const int b1i = r1 >> 10, v1 = r1 & 1023;

    for (int i = tid; i < 112; i += 256) {
        int cc = i / 28, r = i % 28;
        int nt = r >> 2, tg = r & 3;
        int c0 = cc*56 + nt*8 + 2*tg;
        float b0v = (c0     < V_HID) ? B1[c0]     : 0.0f;
        float b1v = (c0 + 1 < V_HID) ? B1[c0 + 1] : 0.0f;
        sb1h[i] = packh2(b0v, b1v);
        float w0v = (c0     < V_HID) ? W1raw[48*V_HID + c0]     : 0.0f;
        float w1v = (c0 + 1 < V_HID) ? W1raw[48*V_HID + c0 + 1] : 0.0f;
        sw1h[i] = packh2(w0v, w1v);
    }
    if (tid < 49) sb2[tid] = B2[tid];

    int p0[3], p1[3];
    #pragma unroll
    for (int e = 0; e < 3; e++) {
        p0[e] = perm[v0*DVd + e];
        p1[e] = perm[v1*DVd + e];
    }
    const float pr0 = prior[v0], pr1 = prior[v1];
    const unsigned pr0h = packh2(pr0, pr0);
    const unsigned pr1h = packh2(pr1, pr1);

    // stage A fragments: kt = e (16 cols per edge)
    {
        const float* base0 = g_Mv + (size_t)b0i*EE*DD;
        const float* base1 = g_Mv + (size_t)b1i*EE*DD;
        uint4* dst = sX + warp*3*32 + lane;
        #pragma unroll
        for (int kt = 0; kt < 3; kt++) {
            const float* q0 = base0 + p0[kt]*DD;
            const float* q1 = base1 + p1[kt]*DD;
            int c = 2*tig;
            float2 p00 = *(const float2*)(q0 + c);
            float2 p01 = *(const float2*)(q0 + c + 8);
            float2 p10 = *(const float2*)(q1 + c);
            float2 p11 = *(const float2*)(q1 + c + 8);
            uint4 v;
            v.x = packh2(p00.x, p00.y);
            v.y = packh2(p10.x, p10.y);
            v.z = packh2(p01.x, p01.y);
            v.w = packh2(p11.x, p11.y);
            dst[kt*32] = v;
        }
    }

    unsigned* sHw = sH + warp*16*SHS;
    for (int i = lane; i < 64; i += 32) {
        int rr = i >> 2, w = 28 + (i & 3);
        sHw[rr*SHS + w] = 0;
    }
    __syncthreads();

    float acc2[7][4];
    #pragma unroll
    for (int n = 0; n < 7; n++)
        #pragma unroll
        for (int i = 0; i < 4; i++) acc2[n][i] = 0.0f;

    const uint4* myX = sX + warp*3*32 + lane;

    for (int cc = 0; cc < 4; cc++) {
        // ---- layer 1 (fp16 acc): K=48, rank-1 prior init ----
        unsigned acc1[7][2];
        #pragma unroll
        for (int nt = 0; nt < 7; nt++) {
            unsigned w = sw1h[cc*28 + nt*4 + tig];
            acc1[nt][0] = hmul2u(pr0h, w);
            acc1[nt][1] = hmul2u(pr1h, w);
        }
        const uint2* wp1 = (const uint2*)g_vW1f + (size_t)cc*672 + lane;
        #pragma unroll
        for (int kt = 0; kt < 3; kt++) {
            uint4 a4 = myX[kt*32];
            unsigned a[4] = {a4.x, a4.y, a4.z, a4.w};
            #pragma unroll
            for (int nt = 0; nt < 7; nt++) {
                uint2 b = __ldg(wp1 + (size_t)(nt*3 + kt)*32);
                mma_f16h(acc1[nt], a, b.x, b.y);
            }
        }

        #pragma unroll
        for (int nt = 0; nt < 7; nt++) {
            unsigned bb = sb1h[cc*28 + nt*4 + tig];
            sHw[gid*SHS      + nt*4 + tig] = gelu_h2p(hadd2u(acc1[nt][0], bb));
            sHw[(gid+8)*SHS  + nt*4 + tig] = gelu_h2p(hadd2u(acc1[nt][1], bb));
        }
        __syncwarp();

        const uint4* wp2 = (const uint4*)g_vW2f + (size_t)cc*448 + lane;
        #pragma unroll
        for (int ktlp = 0; ktlp < 2; ktlp++) {
            int w0 = (2*ktlp)*8 + tig;
            int w1 = w0 + 8;
            unsigned a0[4] = { sHw[gid*SHS + w0],     sHw[(gid+8)*SHS + w0],
                               sHw[gid*SHS + w0 + 4], sHw[(gid+8)*SHS + w0 + 4] };
            unsigned a1[4] = { sHw[gid*SHS + w1],     sHw[(gid+8)*SHS + w1],
                               sHw[gid*SHS + w1 + 4], sHw[(gid+8)*SHS + w1 + 4] };
            #pragma unroll
            for (int nt = 0; nt < 7; nt++) {
                uint4 b = __ldg(wp2 + (size_t)(nt*2 + ktlp)*32);
                mma_f16(acc2[nt], a0, b.x, b.y);
                mma_f16(acc2[nt], a1, b.z, b.w);
            }
        }
        __syncwarp();
    }

    // ---- epilogue: float2 scatter via perm regs; col 48 -> llr ----
    #pragma unroll
    for (int nt = 0; nt < 6; nt++) {
        int col = nt*8 + 2*tig;              // even, < 48
        int e = col >> 4, d = col & 15;
        float bb0 = sb2[col], bb1 = sb2[col+1];
        {
            float2 y;
            y.x = acc2[nt][0] + bb0;
            y.y = acc2[nt][1] + bb1;
            *(float2*)(g_Mc + ((size_t)b0i*EE + p0[e])*DD + d) = y;
        }
        {
            float2 y;
            y.x = acc2[nt][2] + bb0;
            y.y = acc2[nt][3] + bb1;
            *(float2*)(g_Mc + ((size_t)b1i*EE + p1[e])*DD + d) = y;
        }
    }
    if (tig == 0) {
        float bb = sb2[48];
        out_llr[r0] = acc2[6][0] + bb;
        out_llr[r1] = acc2[6][2] + bb;
    }
}

// ---------------------------------------------------------------------------
extern "C" void kernel_launch(void* const* d_in, const int* in_sizes, int n_in,
                              void* d_out, int out_size)
{
    const int*   synd  = (const int*)  d_in[0];
    const float* prior = (const float*)d_in[2];
    const int*   perm  = (const int*)  d_in[3];
    const float* cW1   = (const float*)d_in[4];
    const float* cb1   = (const float*)d_in[5];
    const float* cW2   = (const float*)d_in[6];
    const float* cb2   = (const float*)d_in[7];
    const float* vW1   = (const float*)d_in[8];
    const float* vb1   = (const float*)d_in[9];
    const float* vW2   = (const float*)d_in[10];
    const float* vb2   = (const float*)d_in[11];
    float* out = (float*)d_out;

    const int T = out_size / (BATCH * NVAR);

    const int check_smem = (6144 + 4608 + 196 + 196)*4 + 96*4 + 64;   // ~44.8 KB
    const int var_smem   = (3072 + 4608 + 112 + 112)*4 + 49*4 + 64;   // ~31.8 KB

    cudaFuncSetAttribute(check_kernel, cudaFuncAttributeMaxDynamicSharedMemorySize, check_smem);
    cudaFuncSetAttribute(var_kernel,   cudaFuncAttributeMaxDynamicSharedMemorySize, var_smem);

    prep_voe<<<(EE + 255)/256, 256>>>(perm);
    prep_check<<<(40320 + 255)/256, 256>>>(cW1, cW2);
    prep_var<<<(12544 + 255)/256, 256>>>(vW1, vW2);

    const int check_blocks = (BATCH*NCHK) / 128;   // 1024
    const int var_blocks   = (BATCH*NVAR) / 128;   // 2048

    for (int t = 0; t < T; t++) {
        check_kernel<<<check_blocks, 256, check_smem>>>(synd, cW1, cb1, cb2,
                                                        prior, t == 0 ? 1 : 0);
        var_kernel<<<var_blocks, 256, var_smem>>>(perm, prior, vW1, vb1, vb2,
                                                  out + (size_t)t * BATCH * NVAR);
    }
}